// round 16
// baseline (speedup 1.0000x reference)
#include <cuda_runtime.h>
#include <cuda_bf16.h>

#define DEV_INLINE __device__ __forceinline__
constexpr int BATCH = 4;
constexpr int NBP = 296;          // persistent grid: 2 blocks per SM
constexpr int NTP = 256;          // threads per block
constexpr int NWP = NBP * 8;      // total warps

// ---------------- buffer layout (floats): all activations NHWC padded -----
constexpr int OFF_X    = 0;                                    // [4][34][34][4]
constexpr int OFF_32A  = OFF_X   + BATCH * 34 * 34 * 4;        // [4][34][34][64]
constexpr int OFF_32B  = OFF_32A + BATCH * 34 * 34 * 64;
constexpr int OFF_16A  = OFF_32B + BATCH * 34 * 34 * 64;       // [4][18][18][64]
constexpr int OFF_16B  = OFF_16A + BATCH * 18 * 18 * 64;       // [4][18][18][128]
constexpr int OFF_16C  = OFF_16B + BATCH * 18 * 18 * 128;
constexpr int OFF_8A   = OFF_16C + BATCH * 18 * 18 * 128;      // [4][10][10][128]
constexpr int OFF_8B   = OFF_8A  + BATCH * 10 * 10 * 128;      // [4][10][10][256]
constexpr int OFF_8C   = OFF_8B  + BATCH * 10 * 10 * 256;
constexpr int OFF_4A   = OFF_8C  + BATCH * 10 * 10 * 256;      // [4][6][6][256]
constexpr int OFF_4B   = OFF_4A  + BATCH * 6 * 6 * 256;        // [4][6][6][512]
constexpr int OFF_4C   = OFF_4B  + BATCH * 6 * 6 * 512;
constexpr int OFF_2A   = OFF_4C  + BATCH * 6 * 6 * 512;        // [4][4][4][512]
constexpr int OFF_2B   = OFF_2A  + BATCH * 4 * 4 * 512;
constexpr int OFF_FCS0 = OFF_2B  + BATCH * 4 * 4 * 512;        // [4][4096]
constexpr int OFF_FCS1 = OFF_FCS0 + BATCH * 4096;

// membranes: NHWC dense
constexpr int M0  = OFF_FCS1 + BATCH * 4096;
constexpr int M1  = M0  + BATCH * 32 * 32 * 64;
constexpr int M2  = M1  + BATCH * 32 * 32 * 64;
constexpr int M3  = M2  + BATCH * 16 * 16 * 128;
constexpr int M4  = M3  + BATCH * 16 * 16 * 128;
constexpr int M5  = M4  + BATCH * 8 * 8 * 256;
constexpr int M6  = M5  + BATCH * 8 * 8 * 256;
constexpr int M7  = M6  + BATCH * 8 * 8 * 256;
constexpr int M8  = M7  + BATCH * 4 * 4 * 512;
constexpr int M9  = M8  + BATCH * 4 * 4 * 512;
constexpr int M10 = M9  + BATCH * 4 * 4 * 512;
constexpr int M11 = M10 + BATCH * 2 * 2 * 512;
constexpr int M12 = M11 + BATCH * 2 * 2 * 512;
constexpr int MF0 = M12 + BATCH * 2 * 2 * 512;
constexpr int MF1 = MF0 + BATCH * 4096;
constexpr int TOTAL_BUF = MF1 + BATCH * 4096;

__device__ __align__(16) float g_buf[TOTAL_BUF];

// transposed weights [co][tap][ci] for conv layers 1..12
constexpr long WT1  = 0;
constexpr long WT2  = WT1  + 64L  * 64  * 9;
constexpr long WT3  = WT2  + 128L * 64  * 9;
constexpr long WT4  = WT3  + 128L * 128 * 9;
constexpr long WT5  = WT4  + 256L * 128 * 9;
constexpr long WT6  = WT5  + 256L * 256 * 9;
constexpr long WT7  = WT6  + 256L * 256 * 9;
constexpr long WT8  = WT7  + 512L * 256 * 9;
constexpr long WT9  = WT8  + 512L * 512 * 9;
constexpr long WT10 = WT9  + 512L * 512 * 9;
constexpr long WT11 = WT10 + 512L * 512 * 9;
constexpr long WT12 = WT11 + 512L * 512 * 9;
constexpr long WT_TOTAL = WT12 + 512L * 512 * 9;
__device__ __align__(16) float g_wt[WT_TOTAL];

// ---------------- grid barrier: atomic arrive, volatile-load spin ---------
__device__ unsigned g_cnt = 0;
__device__ unsigned g_rel = 0;

DEV_INLINE void gsync(unsigned e) {
    __syncthreads();
    if (threadIdx.x == 0) {
        __threadfence();
        unsigned v = atomicAdd(&g_cnt, 1u);
        if (v + 1u == e * (unsigned)NBP) {
            __threadfence();
            *(volatile unsigned*)&g_rel = e;
        } else {
            while (*(volatile unsigned*)&g_rel < e) { }
        }
        __threadfence();
    }
    __syncthreads();
}

// ---------------- multi-compartment LIF (K=2), exact ----------------------
DEV_INLINE float lif_fire(float* memp, float syn, float thr, float leak) {
    float m = leak * (*memp) + syn;
    float e0 = m / thr          - 1.0f;
    float o0 = 1.0f - m / (2.0f * thr);
    float e1 = m / (2.0f * thr) - 1.0f;
    float o1 = 1.0f - m / (4.0f * thr);
    float v = 0.0f;
    if (e0 > 0.0f && o0 >= 0.0f) v = 1.0f;
    if (e1 > 0.0f && o1 >= 0.0f) v = 2.0f;
    *memp = m - thr * v;
    return v;
}

// ---------------- pre-kernels ---------------------------------------------
__global__ void k_zero(float* __restrict__ dout) {
    int i = blockIdx.x * blockDim.x + threadIdx.x;
    if (i < TOTAL_BUF) g_buf[i] = 0.0f;
    if (i < BATCH * 10) dout[i] = 0.0f;
}

__global__ void k_pad_x(const float* __restrict__ x) {
    int idx = blockIdx.x * blockDim.x + threadIdx.x;
    if (idx >= BATCH * 3 * 32 * 32) return;
    int xx = idx & 31;
    int y  = (idx >> 5) & 31;
    int c  = (idx >> 10) % 3;
    int b  = idx / (3 * 1024);
    g_buf[OFF_X + (((b * 34) + y + 1) * 34 + (xx + 1)) * 4 + c] = x[idx];
}

struct WP { const float* p[12]; };
__global__ void k_wtrans_all(WP wp) {
    __shared__ float s[4608];
    const int CINs[12]  = {64, 64, 128, 128, 256, 256, 256, 512, 512, 512, 512, 512};
    const int COUTs[12] = {64, 128, 128, 256, 256, 256, 512, 512, 512, 512, 512, 512};
    const long OFFs[12] = {WT1, WT2, WT3, WT4, WT5, WT6, WT7, WT8, WT9, WT10, WT11, WT12};
    int l  = blockIdx.y;
    int co = blockIdx.x;
    int CIN = CINs[l];
    if (co >= COUTs[l]) return;
    const float* src = wp.p[l] + (long)co * CIN * 9;
    float* dst = g_wt + OFFs[l] + (long)co * CIN * 9;
    int n = CIN * 9;
    for (int i = threadIdx.x; i < n; i += 256) s[i] = src[i];
    __syncthreads();
    for (int i = threadIdx.x; i < n; i += 256) {
        int ci = i % CIN, t = i / CIN;
        dst[i] = s[ci * 9 + t];
    }
}

// ---------------- layer 0: CIN=3, warp per pixel, lanes = co --------------
DEV_INLINE void convL0_p(const float* __restrict__ w0,
                         const float* __restrict__ thrp,
                         const float* __restrict__ leakp, float* sw) {
    __syncthreads();
    for (int i = threadIdx.x; i < 64 * 27; i += NTP) {
        int co = i / 27, t = i % 27;
        sw[t * 64 + co] = __ldg(w0 + co * 27 + t);
    }
    __syncthreads();
    int warp = threadIdx.x >> 5, lane = threadIdx.x & 31;
    float thr = __ldg(thrp), leak = __ldg(leakp);
    for (int pj = blockIdx.x * 8 + warp; pj < BATCH * 32 * 32; pj += NBP * 8) {
        int x = pj & 31, y = (pj >> 5) & 31, b = pj >> 10;
        const float* ip = g_buf + OFF_X + (((long)(b * 34) + y) * 34 + x) * 4;
        float iv[27];
#pragma unroll
        for (int dy = 0; dy < 3; dy++)
#pragma unroll
            for (int dx = 0; dx < 3; dx++)
#pragma unroll
                for (int ci = 0; ci < 3; ci++)
                    iv[ci * 9 + dy * 3 + dx] = __ldg(ip + (dy * 34 + dx) * 4 + ci);
        float a0 = 0.f, a1 = 0.f;
#pragma unroll
        for (int t = 0; t < 27; t++) {
            a0 += sw[t * 64 + lane] * iv[t];
            a1 += sw[t * 64 + 32 + lane] * iv[t];
        }
        long o = (((long)(b * 34) + y + 1) * 34 + (x + 1)) * 64;
        long m = (((long)(b * 32) + y) * 32 + x) * 64;
        g_buf[OFF_32A + o + lane] =
            lif_fire(&g_buf[M0 + m + lane], a0, thr, leak);
        g_buf[OFF_32A + o + 32 + lane] =
            lif_fire(&g_buf[M0 + m + 32 + lane], a1, thr, leak);
    }
}

// ---------------- convA: array-form for narrow channels (layers 1..3) -----
// warp = (b, y, x-half); lanes own CPL channels; TW=16 outputs per warp.
// Unpredicated FMA sweep like convG, float2/float4 flavors.
template<int CIN, int CST, int TW, int XH, int COUT, int CPL>
DEV_INLINE void convA_p(int in_off, long wt_off, int mem_off, int out_off,
                        const float* __restrict__ thrp,
                        const float* __restrict__ leakp, float* sw) {
    constexpr int S = TW * XH;
    constexpr int SP = S + 2;
    constexpr int CH = 32 * CPL;
    constexpr int CHUNKS = CIN / CH;
    constexpr int WJOBS = BATCH * S * XH;
    constexpr int PARTS = WJOBS / 8;
    constexpr int NJOBS = COUT * PARTS;
    static_assert(TW <= 32, "one lane per output");
    int warp = threadIdx.x >> 5, lane = threadIdx.x & 31;
    float thr = __ldg(thrp), leak = __ldg(leakp);

    for (int jobi = blockIdx.x; jobi < NJOBS; jobi += NBP) {
        int co   = jobi / PARTS;
        int part = jobi % PARTS;
        int wj = part * 8 + warp;
        int xh = wj % XH;
        int y  = (wj / XH) % S;
        int b  = wj / (XH * S);

        float acc[TW];
#pragma unroll
        for (int x = 0; x < TW; x++) acc[x] = 0.f;

        for (int ch = 0; ch < CHUNKS; ch++) {
            __syncthreads();
            const float* wsrc = g_wt + wt_off + (long)co * CIN * 9 + ch * CH;
            for (int i = threadIdx.x; i < 9 * CH; i += NTP) {
                int t = i / CH, c = i % CH;
                sw[t * CH + c] = __ldg(wsrc + (long)t * CIN + c);
            }
            __syncthreads();

            const float* base = g_buf + in_off + ch * CH + lane * CPL
                              + (long)(xh * TW) * CST;
#pragma unroll
            for (int rr = 0; rr < 3; rr++) {
                const float* rp = base + ((long)(b * SP + y + rr) * SP) * CST;
                float wv[3][CPL];
#pragma unroll
                for (int dx = 0; dx < 3; dx++)
#pragma unroll
                    for (int c = 0; c < CPL; c++)
                        wv[dx][c] = sw[(rr * 3 + dx) * CH + lane * CPL + c];
                float a[TW + 2][CPL];
#pragma unroll
                for (int j = 0; j < TW + 2; j++) {
                    if constexpr (CPL == 2) {
                        float2 v = __ldg((const float2*)(rp + (long)j * CST));
                        a[j][0] = v.x; a[j][1] = v.y;
                    } else {
                        float4 v = __ldg((const float4*)(rp + (long)j * CST));
                        a[j][0] = v.x; a[j][1] = v.y; a[j][2] = v.z; a[j][3] = v.w;
                    }
                }
#pragma unroll
                for (int x = 0; x < TW; x++)
#pragma unroll
                    for (int dx = 0; dx < 3; dx++)
#pragma unroll
                        for (int c = 0; c < CPL; c++)
                            acc[x] += wv[dx][c] * a[x + dx][c];
            }
        }

        float mine = 0.f;
#pragma unroll
        for (int x = 0; x < TW; x++) {
            float v = acc[x];
#pragma unroll
            for (int o = 16; o; o >>= 1)
                v += __shfl_xor_sync(0xffffffffu, v, o);
            if (lane == x) mine = v;
        }
        if (lane < TW) {
            int xg = xh * TW + lane;
            long midx = (((long)b * S + y) * S + xg) * COUT + co;
            long oidx = (((long)b * SP + (y + 1)) * SP + (xg + 1)) * (long)COUT + co;
            g_buf[out_off + oidx] =
                lif_fire(&g_buf[mem_off + midx], mine, thr, leak);
        }
    }
}

// ---------------- convG: NHWC array-form (S<=8) ---------------------------
template<int CIN, int CST, int S, int COUT, int G, int WPB, int PARTS>
DEV_INLINE void convG_p(int in_off, long wt_off, int mem_off, int out_off,
                        const float* __restrict__ thrp,
                        const float* __restrict__ leakp, float* sw) {
    constexpr int SP = S + 2;
    constexpr int CHUNKS = CIN / 128;
    static_assert(WPB * PARTS == BATCH * S, "warps must exactly cover jobs");
    static_assert(WPB == 8, "8 warps per block");
    static_assert(G * S <= 32, "one lane per output");
    int warp = threadIdx.x >> 5, lane = threadIdx.x & 31;
    float thr = __ldg(thrp), leak = __ldg(leakp);
    int cb = lane * 4;

    for (int jobi = blockIdx.x; jobi < (COUT / G) * PARTS; jobi += NBP) {
        int cog  = jobi / PARTS;
        int part = jobi % PARTS;
        int job  = part * WPB + warp;
        int b = job / S, y = job % S;

        float acc[G][S];
#pragma unroll
        for (int g = 0; g < G; g++)
#pragma unroll
            for (int x = 0; x < S; x++) acc[g][x] = 0.f;

        for (int ch = 0; ch < CHUNKS; ch++) {
            __syncthreads();
            const float* wsrc = g_wt + wt_off + ((long)cog * G) * CIN * 9 + ch * 128;
            for (int i = threadIdx.x; i < G * 9 * 32; i += 256) {
                int g = i / (9 * 32);
                int r = i % (9 * 32);
                int t = r / 32, c4 = r % 32;
                *(float4*)(sw + (g * 9 + t) * 128 + c4 * 4) =
                    __ldg((const float4*)(wsrc + ((long)g * 9 + t) * CIN + c4 * 4));
            }
            __syncthreads();

            const float* base = g_buf + in_off + ch * 128 + cb;
#pragma unroll
            for (int rr = 0; rr < 3; rr++) {
                const float* rp = base + ((long)(b * SP + y + rr) * SP) * CST;
                float4 a[S + 2];
#pragma unroll
                for (int j = 0; j < S + 2; j++)
                    a[j] = __ldg((const float4*)(rp + (long)j * CST));
#pragma unroll
                for (int g = 0; g < G; g++) {
                    const float* wrow = sw + (g * 9 + rr * 3) * 128 + cb;
                    float4 w0 = *(const float4*)(wrow);
                    float4 w1 = *(const float4*)(wrow + 128);
                    float4 w2 = *(const float4*)(wrow + 256);
#pragma unroll
                    for (int x = 0; x < S; x++) {
                        float4 a0 = a[x], a1 = a[x + 1], a2 = a[x + 2];
                        acc[g][x] += a0.x*w0.x + a0.y*w0.y + a0.z*w0.z + a0.w*w0.w
                                   + a1.x*w1.x + a1.y*w1.y + a1.z*w1.z + a1.w*w1.w
                                   + a2.x*w2.x + a2.y*w2.y + a2.z*w2.z + a2.w*w2.w;
                    }
                }
            }
        }

        float mine = 0.f;
#pragma unroll
        for (int g = 0; g < G; g++)
#pragma unroll
            for (int x = 0; x < S; x++) {
                float v = acc[g][x];
#pragma unroll
                for (int o = 16; o; o >>= 1)
                    v += __shfl_xor_sync(0xffffffffu, v, o);
                if (lane == g * S + x) mine = v;
            }

        if (lane < G * S) {
            int g = lane / S, x = lane % S;
            int co = cog * G + g;
            long midx = (((long)b * S + y) * S + x) * COUT + co;
            long oidx = (((long)b * SP + (y + 1)) * SP + (x + 1)) * (long)COUT + co;
            g_buf[out_off + oidx] =
                lif_fire(&g_buf[mem_off + midx], mine, thr, leak);
        }
    }
}

// ---------------- pool (NHWC -> NHWC) -------------------------------------
template<int C, int S, int CSTI, int CSTO>
DEV_INLINE void pool_nn_p(int in_off, int out_off) {
    constexpr int SO = S / 2, SPI = S + 2, SPO = SO + 2;
    for (int idx = blockIdx.x * NTP + threadIdx.x; idx < BATCH * C * SO * SO; idx += NBP * NTP) {
        int c = idx % C;
        int x = (idx / C) % SO, y = (idx / (C * SO)) % SO, b = idx / (C * SO * SO);
        const float* p = g_buf + in_off + (((long)b * SPI + 2 * y + 1) * SPI + 2 * x + 1) * CSTI + c;
        float v = 0.25f * (p[0] + p[CSTI] + p[(long)SPI * CSTI] + p[(long)(SPI + 1) * CSTI]);
        g_buf[out_off + (((long)b * SPO + y + 1) * SPO + x + 1) * CSTO + c] = v;
    }
}

// ---------------- fully connected ----------------------------------------
DEV_INLINE void fc0_p(const float* __restrict__ W, int mem_off, int out_off,
                      const float* __restrict__ thrp, const float* __restrict__ leakp) {
    int lane = threadIdx.x & 31;
    int wg0 = blockIdx.x * 8 + (threadIdx.x >> 5);
    float thr = __ldg(thrp), leak = __ldg(leakp);
    const float* src = g_buf + OFF_2B;
    for (int o = wg0; o < 4096; o += NWP) {
        float acc[4] = {0.f, 0.f, 0.f, 0.f};
        for (int c = lane; c < 512; c += 32) {
            float4 wv = __ldg((const float4*)(W + (long)o * 2048 + c * 4));
#pragma unroll
            for (int b = 0; b < 4; b++) {
                long base = ((long)(b * 16 + 5)) * 512 + c;
                float a00 = src[base], a01 = src[base + 512];
                float a10 = src[base + 4 * 512], a11 = src[base + 5 * 512];
                acc[b] += wv.x * a00 + wv.y * a01 + wv.z * a10 + wv.w * a11;
            }
        }
#pragma unroll
        for (int b = 0; b < 4; b++)
#pragma unroll
            for (int of = 16; of; of >>= 1)
                acc[b] += __shfl_xor_sync(0xffffffffu, acc[b], of);
        if (lane == 0)
#pragma unroll
            for (int b = 0; b < 4; b++)
                g_buf[out_off + (long)b * 4096 + o] =
                    lif_fire(&g_buf[mem_off + (long)b * 4096 + o], acc[b], thr, leak);
    }
}

template<int KD>
DEV_INLINE void fc4_p(const float* __restrict__ W, int in_off, int mem_off, int out_off,
                      const float* __restrict__ thrp, const float* __restrict__ leakp,
                      int OUTN) {
    int lane = threadIdx.x & 31;
    int wg0 = blockIdx.x * 8 + (threadIdx.x >> 5);
    float thr = __ldg(thrp), leak = __ldg(leakp);
    const float4* ip = (const float4*)(g_buf + in_off);
    for (int o = wg0; o < OUTN; o += NWP) {
        const float4* wp = (const float4*)(W + (long)o * KD);
        float acc[4] = {0.f, 0.f, 0.f, 0.f};
        for (int k = lane; k < KD / 4; k += 32) {
            float4 wv = __ldg(wp + k);
#pragma unroll
            for (int b = 0; b < 4; b++) {
                float4 a = ip[b * (KD / 4) + k];
                acc[b] += wv.x * a.x + wv.y * a.y + wv.z * a.z + wv.w * a.w;
            }
        }
#pragma unroll
        for (int b = 0; b < 4; b++)
#pragma unroll
            for (int of = 16; of; of >>= 1)
                acc[b] += __shfl_xor_sync(0xffffffffu, acc[b], of);
        if (lane == 0)
#pragma unroll
            for (int b = 0; b < 4; b++)
                g_buf[out_off + (long)b * OUTN + o] =
                    lif_fire(&g_buf[mem_off + (long)b * OUTN + o], acc[b], thr, leak);
    }
}

DEV_INLINE void logits_p(const float* __restrict__ W, int in_off,
                         float* __restrict__ dout) {
    int lane = threadIdx.x & 31;
    int wg0 = blockIdx.x * 8 + (threadIdx.x >> 5);
    const float4* ip = (const float4*)(g_buf + in_off);
    for (int o = wg0; o < 10; o += NWP) {
        const float4* wp = (const float4*)(W + (long)o * 4096);
        float acc[4] = {0.f, 0.f, 0.f, 0.f};
        for (int k = lane; k < 1024; k += 32) {
            float4 wv = __ldg(wp + k);
#pragma unroll
            for (int b = 0; b < 4; b++) {
                float4 a = ip[b * 1024 + k];
                acc[b] += wv.x * a.x + wv.y * a.y + wv.z * a.z + wv.w * a.w;
            }
        }
#pragma unroll
        for (int b = 0; b < 4; b++)
#pragma unroll
            for (int of = 16; of; of >>= 1)
                acc[b] += __shfl_xor_sync(0xffffffffu, acc[b], of);
        if (lane == 0)
#pragma unroll
            for (int b = 0; b < 4; b++)
                dout[b * 10 + o] += acc[b];
    }
}

// ---------------- the persistent network kernel ---------------------------
struct NetArgs {
    const float* w0;
    const float* fc0w; const float* fc1w; const float* fc2w;
    const float* thr; const float* leak;
    float* out;
};

__global__ void __launch_bounds__(NTP, 2) k_net(NetArgs a) {
    __shared__ __align__(16) float sw[4608];
    __shared__ unsigned s_base;
    if (threadIdx.x == 0) s_base = *(volatile unsigned*)&g_rel;
    __syncthreads();
    unsigned e = s_base;

    for (int t = 0; t < 3; t++) {
        convL0_p(a.w0, a.thr + 0, a.leak + 0, sw);
        gsync(++e);
        convA_p<64, 64, 16, 2, 64, 2>(OFF_32A, WT1, M1, OFF_32B, a.thr + 1, a.leak + 1, sw);
        gsync(++e);
        pool_nn_p<64, 32, 64, 64>(OFF_32B, OFF_16A);
        gsync(++e);
        convA_p<64, 64, 16, 1, 128, 2>(OFF_16A, WT2, M2, OFF_16B, a.thr + 2, a.leak + 2, sw);
        gsync(++e);
        convA_p<128, 128, 16, 1, 128, 4>(OFF_16B, WT3, M3, OFF_16C, a.thr + 3, a.leak + 3, sw);
        gsync(++e);
        pool_nn_p<128, 16, 128, 128>(OFF_16C, OFF_8A);
        gsync(++e);
        convG_p<128, 128, 8, 256, 2, 8, 4>(OFF_8A, WT4, M4, OFF_8B, a.thr + 4, a.leak + 4, sw);
        gsync(++e);
        convG_p<256, 256, 8, 256, 2, 8, 4>(OFF_8B, WT5, M5, OFF_8C, a.thr + 5, a.leak + 5, sw);
        gsync(++e);
        convG_p<256, 256, 8, 256, 2, 8, 4>(OFF_8C, WT6, M6, OFF_8B, a.thr + 6, a.leak + 6, sw);
        gsync(++e);
        pool_nn_p<256, 8, 256, 256>(OFF_8B, OFF_4A);
        gsync(++e);
        convG_p<256, 256, 4, 512, 4, 8, 2>(OFF_4A, WT7, M7, OFF_4B, a.thr + 7, a.leak + 7, sw);
        gsync(++e);
        convG_p<512, 512, 4, 512, 4, 8, 2>(OFF_4B, WT8, M8, OFF_4C, a.thr + 8, a.leak + 8, sw);
        gsync(++e);
        convG_p<512, 512, 4, 512, 4, 8, 2>(OFF_4C, WT9, M9, OFF_4B, a.thr + 9, a.leak + 9, sw);
        gsync(++e);
        pool_nn_p<512, 4, 512, 512>(OFF_4B, OFF_2A);
        gsync(++e);
        convG_p<512, 512, 2, 512, 2, 8, 1>(OFF_2A, WT10, M10, OFF_2B, a.thr + 10, a.leak + 10, sw);
        gsync(++e);
        convG_p<512, 512, 2, 512, 2, 8, 1>(OFF_2B, WT11, M11, OFF_2A, a.thr + 11, a.leak + 11, sw);
        gsync(++e);
        convG_p<512, 512, 2, 512, 2, 8, 1>(OFF_2A, WT12, M12, OFF_2B, a.thr + 12, a.leak + 12, sw);
        gsync(++e);
        fc0_p(a.fc0w, MF0, OFF_FCS0, a.thr + 13, a.leak + 13);
        gsync(++e);
        fc4_p<4096>(a.fc1w, OFF_FCS0, MF1, OFF_FCS1, a.thr + 14, a.leak + 14, 4096);
        gsync(++e);
        logits_p(a.fc2w, OFF_FCS1, a.out);
        // next-step L0 touches only OFF_32A/M0 (own staging syncthreads +
        // the gsync after it); logits reads FCS1 — disjoint.
    }
}

// ---------------- launch --------------------------------------------------
static inline int gup(long n, int b) { return (int)((n + b - 1) / b); }

extern "C" void kernel_launch(void* const* d_in, const int* in_sizes, int n_in,
                              void* d_out, int out_size) {
    const float* x = (const float*)d_in[0];
    const float* w[13];
    for (int i = 0; i < 13; i++) w[i] = (const float*)d_in[1 + i];
    const float* fc0w = (const float*)d_in[14];
    const float* fc1w = (const float*)d_in[15];
    const float* fc2w = (const float*)d_in[16];
    const float* thr  = (const float*)d_in[17];
    const float* leak = (const float*)d_in[18];
    float* out = (float*)d_out;

    k_zero<<<gup(TOTAL_BUF, 256), 256>>>(out);
    k_pad_x<<<gup(BATCH * 3 * 1024, 256), 256>>>(x);

    WP wp;
    for (int i = 0; i < 12; i++) wp.p[i] = w[1 + i];
    k_wtrans_all<<<dim3(512, 12), 256>>>(wp);

    NetArgs a;
    a.w0 = w[0];
    a.fc0w = fc0w; a.fc1w = fc1w; a.fc2w = fc2w;
    a.thr = thr; a.leak = leak; a.out = out;
    k_net<<<NBP, NTP>>>(a);
}

// round 17
// speedup vs baseline: 1.1341x; 1.1341x over previous
#include <cuda_runtime.h>
#include <cuda_bf16.h>

#define DEV_INLINE __device__ __forceinline__
constexpr int BATCH = 4;
constexpr int NBP = 296;          // persistent grid: 2 blocks per SM
constexpr int NTP = 256;          // threads per block
constexpr int NWP = NBP * 8;      // total warps

// ---------------- buffer layout (floats): all activations NHWC padded -----
constexpr int OFF_X    = 0;                                    // [4][34][34][4]
constexpr int OFF_32A  = OFF_X   + BATCH * 34 * 34 * 4;        // [4][34][34][64]
constexpr int OFF_32B  = OFF_32A + BATCH * 34 * 34 * 64;
constexpr int OFF_16A  = OFF_32B + BATCH * 34 * 34 * 64;       // [4][18][18][64]
constexpr int OFF_16B  = OFF_16A + BATCH * 18 * 18 * 64;       // [4][18][18][128]
constexpr int OFF_16C  = OFF_16B + BATCH * 18 * 18 * 128;
constexpr int OFF_8A   = OFF_16C + BATCH * 18 * 18 * 128;      // [4][10][10][128]
constexpr int OFF_8B   = OFF_8A  + BATCH * 10 * 10 * 128;      // [4][10][10][256]
constexpr int OFF_8C   = OFF_8B  + BATCH * 10 * 10 * 256;
constexpr int OFF_4A   = OFF_8C  + BATCH * 10 * 10 * 256;      // [4][6][6][256]
constexpr int OFF_4B   = OFF_4A  + BATCH * 6 * 6 * 256;        // [4][6][6][512]
constexpr int OFF_4C   = OFF_4B  + BATCH * 6 * 6 * 512;
constexpr int OFF_2A   = OFF_4C  + BATCH * 6 * 6 * 512;        // [4][4][4][512]
constexpr int OFF_2B   = OFF_2A  + BATCH * 4 * 4 * 512;
constexpr int OFF_FCS0 = OFF_2B  + BATCH * 4 * 4 * 512;        // [4][4096]
constexpr int OFF_FCS1 = OFF_FCS0 + BATCH * 4096;

// membranes: NHWC dense
constexpr int M0  = OFF_FCS1 + BATCH * 4096;
constexpr int M1  = M0  + BATCH * 32 * 32 * 64;
constexpr int M2  = M1  + BATCH * 32 * 32 * 64;
constexpr int M3  = M2  + BATCH * 16 * 16 * 128;
constexpr int M4  = M3  + BATCH * 16 * 16 * 128;
constexpr int M5  = M4  + BATCH * 8 * 8 * 256;
constexpr int M6  = M5  + BATCH * 8 * 8 * 256;
constexpr int M7  = M6  + BATCH * 8 * 8 * 256;
constexpr int M8  = M7  + BATCH * 4 * 4 * 512;
constexpr int M9  = M8  + BATCH * 4 * 4 * 512;
constexpr int M10 = M9  + BATCH * 4 * 4 * 512;
constexpr int M11 = M10 + BATCH * 2 * 2 * 512;
constexpr int M12 = M11 + BATCH * 2 * 2 * 512;
constexpr int MF0 = M12 + BATCH * 2 * 2 * 512;
constexpr int MF1 = MF0 + BATCH * 4096;
constexpr int TOTAL_BUF = MF1 + BATCH * 4096;

__device__ __align__(16) float g_buf[TOTAL_BUF];

// transposed weights [co][tap][ci] for conv layers 1..12
constexpr long WT1  = 0;
constexpr long WT2  = WT1  + 64L  * 64  * 9;
constexpr long WT3  = WT2  + 128L * 64  * 9;
constexpr long WT4  = WT3  + 128L * 128 * 9;
constexpr long WT5  = WT4  + 256L * 128 * 9;
constexpr long WT6  = WT5  + 256L * 256 * 9;
constexpr long WT7  = WT6  + 256L * 256 * 9;
constexpr long WT8  = WT7  + 512L * 256 * 9;
constexpr long WT9  = WT8  + 512L * 512 * 9;
constexpr long WT10 = WT9  + 512L * 512 * 9;
constexpr long WT11 = WT10 + 512L * 512 * 9;
constexpr long WT12 = WT11 + 512L * 512 * 9;
constexpr long WT_TOTAL = WT12 + 512L * 512 * 9;
__device__ __align__(16) float g_wt[WT_TOTAL];

// ---------------- grid barrier: atomic arrive, volatile-load spin ---------
__device__ unsigned g_cnt = 0;
__device__ unsigned g_rel = 0;

DEV_INLINE void gsync(unsigned e) {
    __syncthreads();
    if (threadIdx.x == 0) {
        __threadfence();
        unsigned v = atomicAdd(&g_cnt, 1u);
        if (v + 1u == e * (unsigned)NBP) {
            __threadfence();
            *(volatile unsigned*)&g_rel = e;
        } else {
            while (*(volatile unsigned*)&g_rel < e) { }
        }
        __threadfence();
    }
    __syncthreads();
}

// ---------------- multi-compartment LIF (K=2), exact ----------------------
DEV_INLINE float lif_fire(float* memp, float syn, float thr, float leak) {
    float m = leak * (*memp) + syn;
    float e0 = m / thr          - 1.0f;
    float o0 = 1.0f - m / (2.0f * thr);
    float e1 = m / (2.0f * thr) - 1.0f;
    float o1 = 1.0f - m / (4.0f * thr);
    float v = 0.0f;
    if (e0 > 0.0f && o0 >= 0.0f) v = 1.0f;
    if (e1 > 0.0f && o1 >= 0.0f) v = 2.0f;
    *memp = m - thr * v;
    return v;
}

// ---------------- pre-kernels ---------------------------------------------
__global__ void k_zero(float* __restrict__ dout) {
    int i = blockIdx.x * blockDim.x + threadIdx.x;
    if (i < TOTAL_BUF) g_buf[i] = 0.0f;
    if (i < BATCH * 10) dout[i] = 0.0f;
}

__global__ void k_pad_x(const float* __restrict__ x) {
    int idx = blockIdx.x * blockDim.x + threadIdx.x;
    if (idx >= BATCH * 3 * 32 * 32) return;
    int xx = idx & 31;
    int y  = (idx >> 5) & 31;
    int c  = (idx >> 10) % 3;
    int b  = idx / (3 * 1024);
    g_buf[OFF_X + (((b * 34) + y + 1) * 34 + (xx + 1)) * 4 + c] = x[idx];
}

struct WP { const float* p[12]; };
__global__ void k_wtrans_all(WP wp) {
    __shared__ float s[4608];
    const int CINs[12]  = {64, 64, 128, 128, 256, 256, 256, 512, 512, 512, 512, 512};
    const int COUTs[12] = {64, 128, 128, 256, 256, 256, 512, 512, 512, 512, 512, 512};
    const long OFFs[12] = {WT1, WT2, WT3, WT4, WT5, WT6, WT7, WT8, WT9, WT10, WT11, WT12};
    int l  = blockIdx.y;
    int co = blockIdx.x;
    int CIN = CINs[l];
    if (co >= COUTs[l]) return;
    const float* src = wp.p[l] + (long)co * CIN * 9;
    float* dst = g_wt + OFFs[l] + (long)co * CIN * 9;
    int n = CIN * 9;
    for (int i = threadIdx.x; i < n; i += 256) s[i] = src[i];
    __syncthreads();
    for (int i = threadIdx.x; i < n; i += 256) {
        int ci = i % CIN, t = i / CIN;
        dst[i] = s[ci * 9 + t];
    }
}

// ---------------- layer 0: CIN=3, warp per pixel, lanes = co --------------
DEV_INLINE void convL0_p(const float* __restrict__ w0,
                         const float* __restrict__ thrp,
                         const float* __restrict__ leakp, float* sw) {
    __syncthreads();
    for (int i = threadIdx.x; i < 64 * 27; i += NTP) {
        int co = i / 27, t = i % 27;
        sw[t * 64 + co] = __ldg(w0 + co * 27 + t);
    }
    __syncthreads();
    int warp = threadIdx.x >> 5, lane = threadIdx.x & 31;
    float thr = __ldg(thrp), leak = __ldg(leakp);
    for (int pj = blockIdx.x * 8 + warp; pj < BATCH * 32 * 32; pj += NBP * 8) {
        int x = pj & 31, y = (pj >> 5) & 31, b = pj >> 10;
        const float* ip = g_buf + OFF_X + (((long)(b * 34) + y) * 34 + x) * 4;
        float iv[27];
#pragma unroll
        for (int dy = 0; dy < 3; dy++)
#pragma unroll
            for (int dx = 0; dx < 3; dx++)
#pragma unroll
                for (int ci = 0; ci < 3; ci++)
                    iv[ci * 9 + dy * 3 + dx] = __ldg(ip + (dy * 34 + dx) * 4 + ci);
        float a0 = 0.f, a1 = 0.f;
#pragma unroll
        for (int t = 0; t < 27; t++) {
            a0 += sw[t * 64 + lane] * iv[t];
            a1 += sw[t * 64 + 32 + lane] * iv[t];
        }
        long o = (((long)(b * 34) + y + 1) * 34 + (x + 1)) * 64;
        long m = (((long)(b * 32) + y) * 32 + x) * 64;
        g_buf[OFF_32A + o + lane] =
            lif_fire(&g_buf[M0 + m + lane], a0, thr, leak);
        g_buf[OFF_32A + o + 32 + lane] =
            lif_fire(&g_buf[M0 + m + 32 + lane], a1, thr, leak);
    }
}

// ---------------- convA: array-form, narrow channels, NO smem/syncs -------
// warp = (b, y, x-half); lanes own CPL channels; TW outputs per warp.
// Weights read per-lane straight from g_wt (lane-contiguous, L2-resident).
template<int CIN, int CST, int TW, int XH, int COUT, int CPL>
DEV_INLINE void convA_p(int in_off, long wt_off, int mem_off, int out_off,
                        const float* __restrict__ thrp,
                        const float* __restrict__ leakp) {
    constexpr int S = TW * XH;
    constexpr int SP = S + 2;
    constexpr int CH = 32 * CPL;
    constexpr int CHUNKS = CIN / CH;
    constexpr int PARTS = BATCH * S * XH / 8;
    constexpr int NJOBS = COUT * PARTS;
    static_assert(TW <= 32, "one lane per output");
    int warp = threadIdx.x >> 5, lane = threadIdx.x & 31;
    float thr = __ldg(thrp), leak = __ldg(leakp);

    for (int jobi = blockIdx.x; jobi < NJOBS; jobi += NBP) {
        int co   = jobi / PARTS;
        int part = jobi % PARTS;
        int wj = part * 8 + warp;
        int xh = wj % XH;
        int y  = (wj / XH) % S;
        int b  = wj / (XH * S);

        float acc[TW];
#pragma unroll
        for (int x = 0; x < TW; x++) acc[x] = 0.f;

        for (int ch = 0; ch < CHUNKS; ch++) {
            const float* wbase = g_wt + wt_off + (long)co * CIN * 9
                               + ch * CH + lane * CPL;
            const float* base = g_buf + in_off + ch * CH + lane * CPL
                              + (long)(xh * TW) * CST;
#pragma unroll
            for (int rr = 0; rr < 3; rr++) {
                float wv[3][CPL];
#pragma unroll
                for (int dx = 0; dx < 3; dx++) {
                    const float* wp = wbase + (long)(rr * 3 + dx) * CIN;
                    if constexpr (CPL == 2) {
                        float2 v = __ldg((const float2*)wp);
                        wv[dx][0] = v.x; wv[dx][1] = v.y;
                    } else {
                        float4 v = __ldg((const float4*)wp);
                        wv[dx][0] = v.x; wv[dx][1] = v.y;
                        wv[dx][2] = v.z; wv[dx][3] = v.w;
                    }
                }
                const float* rp = base + ((long)(b * SP + y + rr) * SP) * CST;
                float a[TW + 2][CPL];
#pragma unroll
                for (int j = 0; j < TW + 2; j++) {
                    if constexpr (CPL == 2) {
                        float2 v = __ldg((const float2*)(rp + (long)j * CST));
                        a[j][0] = v.x; a[j][1] = v.y;
                    } else {
                        float4 v = __ldg((const float4*)(rp + (long)j * CST));
                        a[j][0] = v.x; a[j][1] = v.y; a[j][2] = v.z; a[j][3] = v.w;
                    }
                }
#pragma unroll
                for (int x = 0; x < TW; x++)
#pragma unroll
                    for (int dx = 0; dx < 3; dx++)
#pragma unroll
                        for (int c = 0; c < CPL; c++)
                            acc[x] += wv[dx][c] * a[x + dx][c];
            }
        }

        float mine = 0.f;
#pragma unroll
        for (int x = 0; x < TW; x++) {
            float v = acc[x];
#pragma unroll
            for (int o = 16; o; o >>= 1)
                v += __shfl_xor_sync(0xffffffffu, v, o);
            if (lane == x) mine = v;
        }
        if (lane < TW) {
            int xg = xh * TW + lane;
            long midx = (((long)b * S + y) * S + xg) * COUT + co;
            long oidx = (((long)b * SP + (y + 1)) * SP + (xg + 1)) * (long)COUT + co;
            g_buf[out_off + oidx] =
                lif_fire(&g_buf[mem_off + midx], mine, thr, leak);
        }
    }
}

// ---------------- convG: array-form (S<=8), NO smem/syncs -----------------
template<int CIN, int CST, int S, int COUT, int G, int WPB, int PARTS>
DEV_INLINE void convG_p(int in_off, long wt_off, int mem_off, int out_off,
                        const float* __restrict__ thrp,
                        const float* __restrict__ leakp) {
    constexpr int SP = S + 2;
    constexpr int CHUNKS = CIN / 128;
    static_assert(WPB * PARTS == BATCH * S, "warps must exactly cover jobs");
    static_assert(WPB == 8, "8 warps per block");
    static_assert(G * S <= 32, "one lane per output");
    int warp = threadIdx.x >> 5, lane = threadIdx.x & 31;
    float thr = __ldg(thrp), leak = __ldg(leakp);
    int cb = lane * 4;

    for (int jobi = blockIdx.x; jobi < (COUT / G) * PARTS; jobi += NBP) {
        int cog  = jobi / PARTS;
        int part = jobi % PARTS;
        int job  = part * WPB + warp;
        int b = job / S, y = job % S;

        float acc[G][S];
#pragma unroll
        for (int g = 0; g < G; g++)
#pragma unroll
            for (int x = 0; x < S; x++) acc[g][x] = 0.f;

        for (int ch = 0; ch < CHUNKS; ch++) {
            const float* base = g_buf + in_off + ch * 128 + cb;
            const float* wch = g_wt + wt_off + ch * 128 + cb;
#pragma unroll
            for (int rr = 0; rr < 3; rr++) {
                const float* rp = base + ((long)(b * SP + y + rr) * SP) * CST;
                float4 a[S + 2];
#pragma unroll
                for (int j = 0; j < S + 2; j++)
                    a[j] = __ldg((const float4*)(rp + (long)j * CST));
#pragma unroll
                for (int g = 0; g < G; g++) {
                    const float* wrow = wch + ((long)(cog * G + g) * 9 + rr * 3) * CIN;
                    float4 w0 = __ldg((const float4*)(wrow));
                    float4 w1 = __ldg((const float4*)(wrow + CIN));
                    float4 w2 = __ldg((const float4*)(wrow + 2 * CIN));
#pragma unroll
                    for (int x = 0; x < S; x++) {
                        float4 a0 = a[x], a1 = a[x + 1], a2 = a[x + 2];
                        acc[g][x] += a0.x*w0.x + a0.y*w0.y + a0.z*w0.z + a0.w*w0.w
                                   + a1.x*w1.x + a1.y*w1.y + a1.z*w1.z + a1.w*w1.w
                                   + a2.x*w2.x + a2.y*w2.y + a2.z*w2.z + a2.w*w2.w;
                    }
                }
            }
        }

        float mine = 0.f;
#pragma unroll
        for (int g = 0; g < G; g++)
#pragma unroll
            for (int x = 0; x < S; x++) {
                float v = acc[g][x];
#pragma unroll
                for (int o = 16; o; o >>= 1)
                    v += __shfl_xor_sync(0xffffffffu, v, o);
                if (lane == g * S + x) mine = v;
            }

        if (lane < G * S) {
            int g = lane / S, x = lane % S;
            int co = cog * G + g;
            long midx = (((long)b * S + y) * S + x) * COUT + co;
            long oidx = (((long)b * SP + (y + 1)) * SP + (x + 1)) * (long)COUT + co;
            g_buf[out_off + oidx] =
                lif_fire(&g_buf[mem_off + midx], mine, thr, leak);
        }
    }
}

// ---------------- pool (NHWC -> NHWC) -------------------------------------
template<int C, int S, int CSTI, int CSTO>
DEV_INLINE void pool_nn_p(int in_off, int out_off) {
    constexpr int SO = S / 2, SPI = S + 2, SPO = SO + 2;
    for (int idx = blockIdx.x * NTP + threadIdx.x; idx < BATCH * C * SO * SO; idx += NBP * NTP) {
        int c = idx % C;
        int x = (idx / C) % SO, y = (idx / (C * SO)) % SO, b = idx / (C * SO * SO);
        const float* p = g_buf + in_off + (((long)b * SPI + 2 * y + 1) * SPI + 2 * x + 1) * CSTI + c;
        float v = 0.25f * (p[0] + p[CSTI] + p[(long)SPI * CSTI] + p[(long)(SPI + 1) * CSTI]);
        g_buf[out_off + (((long)b * SPO + y + 1) * SPO + x + 1) * CSTO + c] = v;
    }
}

// ---------------- fully connected ----------------------------------------
DEV_INLINE void fc0_p(const float* __restrict__ W, int mem_off, int out_off,
                      const float* __restrict__ thrp, const float* __restrict__ leakp) {
    int lane = threadIdx.x & 31;
    int wg0 = blockIdx.x * 8 + (threadIdx.x >> 5);
    float thr = __ldg(thrp), leak = __ldg(leakp);
    const float* src = g_buf + OFF_2B;
    for (int o = wg0; o < 4096; o += NWP) {
        float acc[4] = {0.f, 0.f, 0.f, 0.f};
        for (int c = lane; c < 512; c += 32) {
            float4 wv = __ldg((const float4*)(W + (long)o * 2048 + c * 4));
#pragma unroll
            for (int b = 0; b < 4; b++) {
                long base = ((long)(b * 16 + 5)) * 512 + c;
                float a00 = src[base], a01 = src[base + 512];
                float a10 = src[base + 4 * 512], a11 = src[base + 5 * 512];
                acc[b] += wv.x * a00 + wv.y * a01 + wv.z * a10 + wv.w * a11;
            }
        }
#pragma unroll
        for (int b = 0; b < 4; b++)
#pragma unroll
            for (int of = 16; of; of >>= 1)
                acc[b] += __shfl_xor_sync(0xffffffffu, acc[b], of);
        if (lane == 0)
#pragma unroll
            for (int b = 0; b < 4; b++)
                g_buf[out_off + (long)b * 4096 + o] =
                    lif_fire(&g_buf[mem_off + (long)b * 4096 + o], acc[b], thr, leak);
    }
}

template<int KD>
DEV_INLINE void fc4_p(const float* __restrict__ W, int in_off, int mem_off, int out_off,
                      const float* __restrict__ thrp, const float* __restrict__ leakp,
                      int OUTN) {
    int lane = threadIdx.x & 31;
    int wg0 = blockIdx.x * 8 + (threadIdx.x >> 5);
    float thr = __ldg(thrp), leak = __ldg(leakp);
    const float4* ip = (const float4*)(g_buf + in_off);
    for (int o = wg0; o < OUTN; o += NWP) {
        const float4* wp = (const float4*)(W + (long)o * KD);
        float acc[4] = {0.f, 0.f, 0.f, 0.f};
        for (int k = lane; k < KD / 4; k += 32) {
            float4 wv = __ldg(wp + k);
#pragma unroll
            for (int b = 0; b < 4; b++) {
                float4 a = ip[b * (KD / 4) + k];
                acc[b] += wv.x * a.x + wv.y * a.y + wv.z * a.z + wv.w * a.w;
            }
        }
#pragma unroll
        for (int b = 0; b < 4; b++)
#pragma unroll
            for (int of = 16; of; of >>= 1)
                acc[b] += __shfl_xor_sync(0xffffffffu, acc[b], of);
        if (lane == 0)
#pragma unroll
            for (int b = 0; b < 4; b++)
                g_buf[out_off + (long)b * OUTN + o] =
                    lif_fire(&g_buf[mem_off + (long)b * OUTN + o], acc[b], thr, leak);
    }
}

DEV_INLINE void logits_p(const float* __restrict__ W, int in_off,
                         float* __restrict__ dout) {
    int lane = threadIdx.x & 31;
    int wg0 = blockIdx.x * 8 + (threadIdx.x >> 5);
    const float4* ip = (const float4*)(g_buf + in_off);
    for (int o = wg0; o < 10; o += NWP) {
        const float4* wp = (const float4*)(W + (long)o * 4096);
        float acc[4] = {0.f, 0.f, 0.f, 0.f};
        for (int k = lane; k < 1024; k += 32) {
            float4 wv = __ldg(wp + k);
#pragma unroll
            for (int b = 0; b < 4; b++) {
                float4 a = ip[b * 1024 + k];
                acc[b] += wv.x * a.x + wv.y * a.y + wv.z * a.z + wv.w * a.w;
            }
        }
#pragma unroll
        for (int b = 0; b < 4; b++)
#pragma unroll
            for (int of = 16; of; of >>= 1)
                acc[b] += __shfl_xor_sync(0xffffffffu, acc[b], of);
        if (lane == 0)
#pragma unroll
            for (int b = 0; b < 4; b++)
                dout[b * 10 + o] += acc[b];
    }
}

// ---------------- the persistent network kernel ---------------------------
struct NetArgs {
    const float* w0;
    const float* fc0w; const float* fc1w; const float* fc2w;
    const float* thr; const float* leak;
    float* out;
};

__global__ void __launch_bounds__(NTP, 2) k_net(NetArgs a) {
    __shared__ __align__(16) float sw[1728];   // L0 weights only
    __shared__ unsigned s_base;
    if (threadIdx.x == 0) s_base = *(volatile unsigned*)&g_rel;
    __syncthreads();
    unsigned e = s_base;

    for (int t = 0; t < 3; t++) {
        convL0_p(a.w0, a.thr + 0, a.leak + 0, sw);
        gsync(++e);
        convA_p<64, 64, 16, 2, 64, 2>(OFF_32A, WT1, M1, OFF_32B, a.thr + 1, a.leak + 1);
        gsync(++e);
        pool_nn_p<64, 32, 64, 64>(OFF_32B, OFF_16A);
        gsync(++e);
        convA_p<64, 64, 16, 1, 128, 2>(OFF_16A, WT2, M2, OFF_16B, a.thr + 2, a.leak + 2);
        gsync(++e);
        convA_p<128, 128, 16, 1, 128, 4>(OFF_16B, WT3, M3, OFF_16C, a.thr + 3, a.leak + 3);
        gsync(++e);
        pool_nn_p<128, 16, 128, 128>(OFF_16C, OFF_8A);
        gsync(++e);
        convG_p<128, 128, 8, 256, 2, 8, 4>(OFF_8A, WT4, M4, OFF_8B, a.thr + 4, a.leak + 4);
        gsync(++e);
        convG_p<256, 256, 8, 256, 2, 8, 4>(OFF_8B, WT5, M5, OFF_8C, a.thr + 5, a.leak + 5);
        gsync(++e);
        convG_p<256, 256, 8, 256, 2, 8, 4>(OFF_8C, WT6, M6, OFF_8B, a.thr + 6, a.leak + 6);
        gsync(++e);
        pool_nn_p<256, 8, 256, 256>(OFF_8B, OFF_4A);
        gsync(++e);
        convG_p<256, 256, 4, 512, 4, 8, 2>(OFF_4A, WT7, M7, OFF_4B, a.thr + 7, a.leak + 7);
        gsync(++e);
        convG_p<512, 512, 4, 512, 4, 8, 2>(OFF_4B, WT8, M8, OFF_4C, a.thr + 8, a.leak + 8);
        gsync(++e);
        convG_p<512, 512, 4, 512, 4, 8, 2>(OFF_4C, WT9, M9, OFF_4B, a.thr + 9, a.leak + 9);
        gsync(++e);
        pool_nn_p<512, 4, 512, 512>(OFF_4B, OFF_2A);
        gsync(++e);
        convG_p<512, 512, 2, 512, 2, 8, 1>(OFF_2A, WT10, M10, OFF_2B, a.thr + 10, a.leak + 10);
        gsync(++e);
        convG_p<512, 512, 2, 512, 2, 8, 1>(OFF_2B, WT11, M11, OFF_2A, a.thr + 11, a.leak + 11);
        gsync(++e);
        convG_p<512, 512, 2, 512, 2, 8, 1>(OFF_2A, WT12, M12, OFF_2B, a.thr + 12, a.leak + 12);
        gsync(++e);
        fc0_p(a.fc0w, MF0, OFF_FCS0, a.thr + 13, a.leak + 13);
        gsync(++e);
        fc4_p<4096>(a.fc1w, OFF_FCS0, MF1, OFF_FCS1, a.thr + 14, a.leak + 14, 4096);
        gsync(++e);
        logits_p(a.fc2w, OFF_FCS1, a.out);
        // next-step L0 touches only OFF_32A/M0 (own staging syncthreads +
        // the gsync after it); logits reads FCS1 — disjoint.
    }
}

// ---------------- launch --------------------------------------------------
static inline int gup(long n, int b) { return (int)((n + b - 1) / b); }

extern "C" void kernel_launch(void* const* d_in, const int* in_sizes, int n_in,
                              void* d_out, int out_size) {
    const float* x = (const float*)d_in[0];
    const float* w[13];
    for (int i = 0; i < 13; i++) w[i] = (const float*)d_in[1 + i];
    const float* fc0w = (const float*)d_in[14];
    const float* fc1w = (const float*)d_in[15];
    const float* fc2w = (const float*)d_in[16];
    const float* thr  = (const float*)d_in[17];
    const float* leak = (const float*)d_in[18];
    float* out = (float*)d_out;

    k_zero<<<gup(TOTAL_BUF, 256), 256>>>(out);
    k_pad_x<<<gup(BATCH * 3 * 1024, 256), 256>>>(x);

    WP wp;
    for (int i = 0; i < 12; i++) wp.p[i] = w[1 + i];
    k_wtrans_all<<<dim3(512, 12), 256>>>(wp);

    NetArgs a;
    a.w0 = w[0];
    a.fc0w = fc0w; a.fc1w = fc1w; a.fc2w = fc2w;
    a.thr = thr; a.leak = leak; a.out = out;
    k_net<<<NBP, NTP>>>(a);
}